// round 1
// baseline (speedup 1.0000x reference)
#include <cuda_runtime.h>
#include <math.h>

// Problem constants
#define Bq 4
#define Tq 2048
#define Cq 2048
#define Hq 32
#define HSq 64
#define Mq (Bq*Tq)            // 8192 tokens
#define DW 128
#define DA 128
#define DG 224
#define DV 64
#define EPS_GN 0.00064f

// ---------------------------------------------------------------------------
// Scratch (static device globals -- allocation-free per harness rules)
// ---------------------------------------------------------------------------
#define BTC ((size_t)Mq*Cq)   // 16,777,216 elements
__device__ float g_xr[BTC];
__device__ float g_xw[BTC];
__device__ float g_xk[BTC];
__device__ float g_xv[BTC];
__device__ float g_xa[BTC];
__device__ float g_xg[BTC];
__device__ float g_r [BTC];
__device__ float g_k [BTC];
__device__ float g_v [BTC];
__device__ float g_dec[BTC];  // decay = exp(-exp(w))
__device__ float g_a [BTC];   // sigmoid icl rate
__device__ float g_g [BTC];   // gate
__device__ float g_kk[BTC];
__device__ float g_y [BTC];
__device__ float g_z [BTC];
__device__ float g_tw[(size_t)Mq*DW];
__device__ float g_ta[(size_t)Mq*DA];
__device__ float g_tv[(size_t)Mq*DV];
__device__ float g_tg[(size_t)Mq*DG];

__device__ __forceinline__ float sigmoidf_(float x){ return 1.0f/(1.0f+expf(-x)); }

// ---------------------------------------------------------------------------
// 1) Token-shift mix: xm = x + (xprev - x) * coef   (6 outputs)
// ---------------------------------------------------------------------------
__global__ void mix_kernel(const float* __restrict__ x,
                           const float* __restrict__ cr, const float* __restrict__ cw,
                           const float* __restrict__ ck, const float* __restrict__ cv,
                           const float* __restrict__ ca, const float* __restrict__ cg,
                           float* __restrict__ xr, float* __restrict__ xw,
                           float* __restrict__ xk, float* __restrict__ xv,
                           float* __restrict__ xa, float* __restrict__ xg)
{
    size_t i4 = (size_t)blockIdx.x*blockDim.x + threadIdx.x;   // float4 index
    size_t n4 = BTC/4;
    if (i4 >= n4) return;
    size_t flat = i4*4;
    int tok = (int)(flat / Cq);
    int t   = tok % Tq;
    const float4* x4 = (const float4*)x;
    float4 xc = x4[i4];
    float4 xp = (t==0) ? make_float4(0,0,0,0) : x4[i4 - Cq/4];
    float4 dx = make_float4(xp.x-xc.x, xp.y-xc.y, xp.z-xc.z, xp.w-xc.w);
    size_t c4 = i4 % (Cq/4);
    #define MIX1(COEF, OUT) { \
        float4 cf = ((const float4*)COEF)[c4]; \
        float4 o = make_float4(xc.x + dx.x*cf.x, xc.y + dx.y*cf.y, \
                               xc.z + dx.z*cf.z, xc.w + dx.w*cf.w); \
        ((float4*)OUT)[i4] = o; }
    MIX1(cr, xr) MIX1(cw, xw) MIX1(ck, xk) MIX1(cv, xv) MIX1(ca, xa) MIX1(cg, xg)
    #undef MIX1
}

// ---------------------------------------------------------------------------
// 2) fp32 SIMT GEMM: C[m,n] = sum_k A[m,k] * B(n,k)
//    BNK=1: B is [N,K] row-major (weights stored (out,in), used as x @ W.T)
//    BNK=0: B is [K,N] row-major (lora matrices)
//    Epilogues: 0 none, 1 tanh, 2 sigmoid, 3 w->decay, 4 a-sigmoid, 5 v-mix
// ---------------------------------------------------------------------------
#define GBM 128
#define GBN 64
#define GBK 16

template<int EPI, int BNK>
__global__ __launch_bounds__(256)
void gemm_k(const float* __restrict__ A, const float* __restrict__ Bm,
            float* __restrict__ Cm, int Md, int Nd, int Kd,
            const float* __restrict__ bias,
            const float* __restrict__ vold, const float* __restrict__ vfirst)
{
    __shared__ __align__(16) float As[GBK][GBM+4];
    __shared__ __align__(16) float Bs[GBK][GBN+4];
    const int bm = blockIdx.y * GBM;
    const int bn = blockIdx.x * GBN;
    const int tid = threadIdx.x;
    const int ty = tid >> 4;          // 0..15 -> 8 rows each
    const int tx = tid & 15;          // 0..15 -> 4 cols each
    float acc[8][4];
    #pragma unroll
    for (int i=0;i<8;i++)
        #pragma unroll
        for (int j=0;j<4;j++) acc[i][j]=0.f;

    for (int k0 = 0; k0 < Kd; k0 += GBK) {
        // --- load A tile (128x16), transposed into As[k][m] ---
        #pragma unroll
        for (int it=0; it<2; it++) {
            int f4  = tid*2 + it;          // 0..511
            int row = f4 >> 2;             // 0..127
            int kc  = (f4 & 3) * 4;        // 0,4,8,12
            float4 vA = *(const float4*)&A[(size_t)(bm+row)*Kd + k0 + kc];
            As[kc+0][row]=vA.x; As[kc+1][row]=vA.y; As[kc+2][row]=vA.z; As[kc+3][row]=vA.w;
        }
        // --- load B tile ---
        if (BNK) {   // B[N,K]: 64 rows x 16 cols
            int row = tid >> 2;            // 0..63
            int kc  = (tid & 3) * 4;
            int gn  = bn + row;
            float4 vB = (gn < Nd) ? *(const float4*)&Bm[(size_t)gn*Kd + k0 + kc]
                                  : make_float4(0,0,0,0);
            Bs[kc+0][row]=vB.x; Bs[kc+1][row]=vB.y; Bs[kc+2][row]=vB.z; Bs[kc+3][row]=vB.w;
        } else {     // B[K,N]: 16 rows x 64 cols
            int kr = tid >> 4;             // 0..15
            int nc = (tid & 15) * 4;
            int gn = bn + nc;
            float4 vB = (gn < Nd) ? *(const float4*)&Bm[(size_t)(k0+kr)*Nd + gn]
                                  : make_float4(0,0,0,0);
            *(float4*)&Bs[kr][nc] = vB;
        }
        __syncthreads();
        // --- compute ---
        #pragma unroll
        for (int kk=0; kk<GBK; kk++) {
            float a[8], b[4];
            *(float4*)&a[0] = *(const float4*)&As[kk][ty*8];
            *(float4*)&a[4] = *(const float4*)&As[kk][ty*8+4];
            *(float4*)&b[0] = *(const float4*)&Bs[kk][tx*4];
            #pragma unroll
            for (int i=0;i<8;i++)
                #pragma unroll
                for (int j=0;j<4;j++)
                    acc[i][j] += a[i]*b[j];
        }
        __syncthreads();
    }

    // --- epilogue + store ---
    #pragma unroll
    for (int i=0;i<8;i++) {
        int m = bm + ty*8 + i;
        #pragma unroll
        for (int j=0;j<4;j++) {
            int n = bn + tx*4 + j;
            if (n >= Nd) continue;
            float val = acc[i][j];
            if (EPI==1) { val = tanhf(val); }
            else if (EPI==2) { val = sigmoidf_(val); }
            else if (EPI==3) {
                float w = bias[n] + val;
                float mneg = -w;
                float sp = fmaxf(mneg,0.f) + log1pf(expf(-fabsf(mneg)));
                float wl = -sp - 0.5f;         // soft-clamped log-decay
                val = expf(-expf(wl));         // decay in (0,1)
            }
            else if (EPI==4) { val = sigmoidf_(bias[n] + val); }
            else if (EPI==5) {
                float s  = sigmoidf_(bias[n] + val);
                size_t idx = (size_t)m*Nd + n;
                float vo = vold[idx];
                val = vo + (vfirst[idx] - vo)*s;
            }
            Cm[(size_t)m*Nd + n] = val;
        }
    }
}

// ---------------------------------------------------------------------------
// 3) kk normalize + k transform (one warp per (token, head))
// ---------------------------------------------------------------------------
__global__ void kk_kernel(float* __restrict__ k, const float* __restrict__ a,
                          const float* __restrict__ k_k, const float* __restrict__ k_a,
                          float* __restrict__ kk)
{
    int gw   = blockIdx.x*8 + (threadIdx.x>>5);  // global head index over Mq*Hq
    int lane = threadIdx.x & 31;
    int m = gw >> 5;        // /Hq
    int h = gw & 31;        // %Hq
    size_t base = (size_t)m*Cq + h*HSq;
    int c0 = h*HSq + lane, c1 = c0 + 32;
    float k0 = k[base+lane], k1 = k[base+lane+32];
    float kk0 = k0*k_k[c0], kk1 = k1*k_k[c1];
    float s = kk0*kk0 + kk1*kk1;
    #pragma unroll
    for (int off=16; off; off>>=1) s += __shfl_xor_sync(0xffffffffu, s, off);
    float inv = 1.0f / fmaxf(sqrtf(s), 1e-12f);
    kk[base+lane]    = kk0*inv;
    kk[base+lane+32] = kk1*inv;
    float a0 = a[base+lane], a1 = a[base+lane+32];
    k[base+lane]    = k0*(1.0f + (a0-1.0f)*k_a[c0]);
    k[base+lane+32] = k1*(1.0f + (a1-1.0f)*k_a[c1]);
}

// ---------------------------------------------------------------------------
// 4) WKV7 sequential scan. One block per (b,h), 64 threads; thread i owns
//    state row i (64 fp32 registers).
//    step: sa_i = <state_i, a>;  state_i = state_i*w + v_i*k + sa_i*b;
//          out_i = <state_i, r>   with a=-kk, b=kk*a_icl
// ---------------------------------------------------------------------------
__global__ __launch_bounds__(64)
void wkv_kernel(const float* __restrict__ r, const float* __restrict__ wd,
                const float* __restrict__ k, const float* __restrict__ v,
                const float* __restrict__ kkp, const float* __restrict__ ap,
                float* __restrict__ y)
{
    int bh = blockIdx.x;
    int b = bh >> 5;         // /Hq
    int h = bh & 31;
    int i = threadIdx.x;
    __shared__ __align__(16) float sr[64], sw[64], sk[64], sa[64], sb[64];
    float st[64];
    #pragma unroll
    for (int j=0;j<64;j++) st[j]=0.f;
    size_t base = ((size_t)b*Tq)*Cq + (size_t)h*HSq;

    for (int t=0; t<Tq; t++) {
        size_t o = base + (size_t)t*Cq;
        float kkv = kkp[o+i];
        sr[i] = r[o+i];
        sw[i] = wd[o+i];
        sk[i] = k[o+i];
        sa[i] = -kkv;
        sb[i] = kkv * ap[o+i];
        float vv = v[o+i];
        __syncthreads();

        // sa_i = <state_i, a>  (4 partial chains for ILP)
        float s0=0,s1=0,s2=0,s3=0;
        const float4* A4 = (const float4*)sa;
        #pragma unroll
        for (int j=0;j<16;j++) {
            float4 a4 = A4[j];
            s0 += st[4*j+0]*a4.x; s1 += st[4*j+1]*a4.y;
            s2 += st[4*j+2]*a4.z; s3 += st[4*j+3]*a4.w;
        }
        float sav = (s0+s1)+(s2+s3);

        const float4* W4=(const float4*)sw; const float4* K4=(const float4*)sk;
        const float4* B4=(const float4*)sb; const float4* R4=(const float4*)sr;
        float o0=0,o1=0,o2=0,o3=0;
        #pragma unroll
        for (int j=0;j<16;j++) {
            float4 w4=W4[j], k4=K4[j], b4=B4[j], r4=R4[j];
            float t0 = st[4*j+0]*w4.x + vv*k4.x + sav*b4.x;
            float t1 = st[4*j+1]*w4.y + vv*k4.y + sav*b4.y;
            float t2 = st[4*j+2]*w4.z + vv*k4.z + sav*b4.z;
            float t3 = st[4*j+3]*w4.w + vv*k4.w + sav*b4.w;
            st[4*j+0]=t0; st[4*j+1]=t1; st[4*j+2]=t2; st[4*j+3]=t3;
            o0 += t0*r4.x; o1 += t1*r4.y; o2 += t2*r4.z; o3 += t3*r4.w;
        }
        y[o+i] = (o0+o1)+(o2+o3);
        __syncthreads();
    }
}

// ---------------------------------------------------------------------------
// 5) GroupNorm (per token, per head) + bonus + gate -> z
// ---------------------------------------------------------------------------
__global__ void gn_kernel(const float* __restrict__ y, const float* __restrict__ r,
                          const float* __restrict__ k, const float* __restrict__ v,
                          const float* __restrict__ g,
                          const float* __restrict__ lnw, const float* __restrict__ lnb,
                          const float* __restrict__ r_k, float* __restrict__ z)
{
    int gw   = blockIdx.x*8 + (threadIdx.x>>5);
    int lane = threadIdx.x & 31;
    int m = gw >> 5;
    int h = gw & 31;
    size_t base = (size_t)m*Cq + h*HSq;
    int c0 = h*HSq + lane, c1 = c0 + 32;
    float y0=y[base+lane], y1=y[base+lane+32];
    float r0=r[base+lane], r1=r[base+lane+32];
    float k0=k[base+lane], k1=k[base+lane+32];
    float sum = y0+y1;
    float sq  = y0*y0 + y1*y1;
    float dot = r0*k0*r_k[c0] + r1*k1*r_k[c1];
    #pragma unroll
    for (int off=16; off; off>>=1) {
        sum += __shfl_xor_sync(0xffffffffu, sum, off);
        sq  += __shfl_xor_sync(0xffffffffu, sq , off);
        dot += __shfl_xor_sync(0xffffffffu, dot, off);
    }
    float mean = sum * (1.0f/64.0f);
    float var  = sq * (1.0f/64.0f) - mean*mean;
    float inv  = rsqrtf(var + EPS_GN);
    float v0=v[base+lane], v1=v[base+lane+32];
    float g0=g[base+lane], g1=g[base+lane+32];
    float z0 = ((y0-mean)*inv*lnw[c0] + lnb[c0] + dot*v0) * g0;
    float z1 = ((y1-mean)*inv*lnw[c1] + lnb[c1] + dot*v1) * g1;
    z[base+lane]    = z0;
    z[base+lane+32] = z1;
}

// ---------------------------------------------------------------------------
// Launch
// ---------------------------------------------------------------------------
extern "C" void kernel_launch(void* const* d_in, const int* in_sizes, int n_in,
                              void* d_out, int out_size)
{
    const float* x       = (const float*)d_in[0];
    const float* v_first = (const float*)d_in[1];
    const float* x_r = (const float*)d_in[2];
    const float* x_w = (const float*)d_in[3];
    const float* x_k = (const float*)d_in[4];
    const float* x_v = (const float*)d_in[5];
    const float* x_a = (const float*)d_in[6];
    const float* x_g = (const float*)d_in[7];
    const float* w0  = (const float*)d_in[8];
    const float* w1  = (const float*)d_in[9];
    const float* w2  = (const float*)d_in[10];
    const float* a0  = (const float*)d_in[11];
    const float* a1  = (const float*)d_in[12];
    const float* a2  = (const float*)d_in[13];
    const float* v0  = (const float*)d_in[14];
    const float* v1  = (const float*)d_in[15];
    const float* v2  = (const float*)d_in[16];
    const float* g1  = (const float*)d_in[17];
    const float* g2  = (const float*)d_in[18];
    const float* k_k = (const float*)d_in[19];
    const float* k_a = (const float*)d_in[20];
    const float* r_k = (const float*)d_in[21];
    const float* Wr  = (const float*)d_in[22];
    const float* Wk  = (const float*)d_in[23];
    const float* Wv  = (const float*)d_in[24];
    const float* Wo  = (const float*)d_in[25];
    const float* lnw = (const float*)d_in[26];
    const float* lnb = (const float*)d_in[27];
    float* out = (float*)d_out;

    float *xr,*xw,*xk,*xv,*xa,*xg,*rB,*kB,*vB,*dec,*aB,*gB,*kkB,*yB,*zB,*tw,*ta,*tv,*tg;
    cudaGetSymbolAddress((void**)&xr , g_xr);
    cudaGetSymbolAddress((void**)&xw , g_xw);
    cudaGetSymbolAddress((void**)&xk , g_xk);
    cudaGetSymbolAddress((void**)&xv , g_xv);
    cudaGetSymbolAddress((void**)&xa , g_xa);
    cudaGetSymbolAddress((void**)&xg , g_xg);
    cudaGetSymbolAddress((void**)&rB , g_r);
    cudaGetSymbolAddress((void**)&kB , g_k);
    cudaGetSymbolAddress((void**)&vB , g_v);
    cudaGetSymbolAddress((void**)&dec, g_dec);
    cudaGetSymbolAddress((void**)&aB , g_a);
    cudaGetSymbolAddress((void**)&gB , g_g);
    cudaGetSymbolAddress((void**)&kkB, g_kk);
    cudaGetSymbolAddress((void**)&yB , g_y);
    cudaGetSymbolAddress((void**)&zB , g_z);
    cudaGetSymbolAddress((void**)&tw , g_tw);
    cudaGetSymbolAddress((void**)&ta , g_ta);
    cudaGetSymbolAddress((void**)&tv , g_tv);
    cudaGetSymbolAddress((void**)&tg , g_tg);

    // 1) token-shift mixes
    mix_kernel<<<(unsigned)((BTC/4 + 255)/256), 256>>>(x, x_r,x_w,x_k,x_v,x_a,x_g,
                                                       xr,xw,xk,xv,xa,xg);

    dim3 gBig((Cq+GBN-1)/GBN, Mq/GBM);     // (32, 64)
    // 2) big projections  (B is [N,K])
    gemm_k<0,1><<<gBig,256>>>(xr, Wr, rB, Mq, Cq, Cq, nullptr,nullptr,nullptr);
    gemm_k<0,1><<<gBig,256>>>(xk, Wk, kB, Mq, Cq, Cq, nullptr,nullptr,nullptr);
    gemm_k<0,1><<<gBig,256>>>(xv, Wv, vB, Mq, Cq, Cq, nullptr,nullptr,nullptr);

    // 3) loras (B is [K,N])
    gemm_k<1,0><<<dim3((DW+GBN-1)/GBN, Mq/GBM),256>>>(xw, w1, tw, Mq, DW, Cq, nullptr,nullptr,nullptr);
    gemm_k<3,0><<<gBig,256>>>(tw, w2, dec, Mq, Cq, DW, w0, nullptr,nullptr);
    gemm_k<0,0><<<dim3((DA+GBN-1)/GBN, Mq/GBM),256>>>(xa, a1, ta, Mq, DA, Cq, nullptr,nullptr,nullptr);
    gemm_k<4,0><<<gBig,256>>>(ta, a2, aB, Mq, Cq, DA, a0, nullptr,nullptr);
    gemm_k<0,0><<<dim3((DV+GBN-1)/GBN, Mq/GBM),256>>>(xv, v1, tv, Mq, DV, Cq, nullptr,nullptr,nullptr);
    gemm_k<5,0><<<gBig,256>>>(tv, v2, vB, Mq, Cq, DV, v0, vB, v_first);
    gemm_k<2,0><<<dim3((DG+GBN-1)/GBN, Mq/GBM),256>>>(xg, g1, tg, Mq, DG, Cq, nullptr,nullptr,nullptr);
    gemm_k<0,0><<<gBig,256>>>(tg, g2, gB, Mq, Cq, DG, nullptr,nullptr,nullptr);

    // 4) kk normalize + k transform
    kk_kernel<<<Mq*Hq/8, 256>>>(kB, aB, k_k, k_a, kkB);

    // 5) WKV7 scan
    wkv_kernel<<<Bq*Hq, 64>>>(rB, dec, kB, vB, kkB, aB, yB);

    // 6) GroupNorm + bonus + gate
    gn_kernel<<<Mq*Hq/8, 256>>>(yB, rB, kB, vB, gB, lnw, lnb, r_k, zB);

    // 7) output projection
    gemm_k<0,1><<<gBig,256>>>(zB, Wo, out, Mq, Cq, Cq, nullptr,nullptr,nullptr);
}

// round 2
// speedup vs baseline: 2.0238x; 2.0238x over previous
#include <cuda_runtime.h>
#include <math.h>
#include <stdint.h>

// Problem constants
#define Bq 4
#define Tq 2048
#define Cq 2048
#define Hq 32
#define HSq 64
#define Mq (Bq*Tq)            // 8192 tokens
#define DW 128
#define DA 128
#define DG 224
#define DV 64
#define EPS_GN 0.00064f

// ---------------------------------------------------------------------------
// Scratch (static device globals -- allocation-free per harness rules)
// ---------------------------------------------------------------------------
#define BTC ((size_t)Mq*Cq)   // 16,777,216 elements
__device__ float g_xr[BTC];
__device__ float g_xw[BTC];
__device__ float g_xk[BTC];
__device__ float g_xv[BTC];
__device__ float g_xa[BTC];
__device__ float g_xg[BTC];
__device__ float g_r [BTC];
__device__ float g_k [BTC];
__device__ float g_v [BTC];
__device__ float g_dec[BTC];
__device__ float g_a [BTC];
__device__ float g_g [BTC];
__device__ float g_kk[BTC];
__device__ float g_y [BTC];
__device__ float g_z [BTC];
__device__ float g_tw[(size_t)Mq*DW];
__device__ float g_ta[(size_t)Mq*DA];
__device__ float g_tv[(size_t)Mq*DV];
__device__ float g_tg[(size_t)Mq*DG];
// tf32-rounded weights
__device__ float g_Wrt[(size_t)Cq*Cq];
__device__ float g_Wkt[(size_t)Cq*Cq];
__device__ float g_Wvt[(size_t)Cq*Cq];
__device__ float g_Wot[(size_t)Cq*Cq];
__device__ float g_w1t[(size_t)Cq*DW];
__device__ float g_w2t[(size_t)DW*Cq];
__device__ float g_a1t[(size_t)Cq*DA];
__device__ float g_a2t[(size_t)DA*Cq];
__device__ float g_v1t[(size_t)Cq*DV];
__device__ float g_v2t[(size_t)DV*Cq];
__device__ float g_g1t[(size_t)Cq*DG];
__device__ float g_g2t[(size_t)DG*Cq];

__device__ __forceinline__ float sigmoidf_(float x){ return 1.0f/(1.0f+expf(-x)); }

__device__ __forceinline__ float to_tf32(float x){
    uint32_t u;
    asm("cvt.rna.tf32.f32 %0, %1;" : "=r"(u) : "f"(x));
    return __uint_as_float(u);
}

__device__ __forceinline__ uint32_t sptr(const void* p){
    return (uint32_t)__cvta_generic_to_shared(p);
}
__device__ __forceinline__ void cpa16(uint32_t s, const void* g, int srcsize){
    asm volatile("cp.async.cg.shared.global [%0], [%1], 16, %2;\n"
                 :: "r"(s), "l"(g), "r"(srcsize));
}

__device__ __forceinline__ void mma8(float* c, const uint32_t* a, const uint32_t* b){
    asm volatile("mma.sync.aligned.m16n8k8.row.col.f32.tf32.tf32.f32 "
        "{%0,%1,%2,%3},{%4,%5,%6,%7},{%8,%9},{%0,%1,%2,%3};\n"
        : "+f"(c[0]),"+f"(c[1]),"+f"(c[2]),"+f"(c[3])
        : "r"(a[0]),"r"(a[1]),"r"(a[2]),"r"(a[3]),"r"(b[0]),"r"(b[1]));
}

// ---------------------------------------------------------------------------
// tf32 rounding pass for weights
// ---------------------------------------------------------------------------
__global__ void round_kernel(const float* __restrict__ in, float* __restrict__ out, size_t n4)
{
    size_t i = (size_t)blockIdx.x*blockDim.x + threadIdx.x;
    if (i >= n4) return;
    float4 v = ((const float4*)in)[i];
    v.x = to_tf32(v.x); v.y = to_tf32(v.y); v.z = to_tf32(v.z); v.w = to_tf32(v.w);
    ((float4*)out)[i] = v;
}

// ---------------------------------------------------------------------------
// 1) Token-shift mix (outputs tf32-rounded)
// ---------------------------------------------------------------------------
__global__ void mix_kernel(const float* __restrict__ x,
                           const float* __restrict__ cr, const float* __restrict__ cw,
                           const float* __restrict__ ck, const float* __restrict__ cv,
                           const float* __restrict__ ca, const float* __restrict__ cg,
                           float* __restrict__ xr, float* __restrict__ xw,
                           float* __restrict__ xk, float* __restrict__ xv,
                           float* __restrict__ xa, float* __restrict__ xg)
{
    size_t i4 = (size_t)blockIdx.x*blockDim.x + threadIdx.x;
    size_t n4 = BTC/4;
    if (i4 >= n4) return;
    size_t flat = i4*4;
    int tok = (int)(flat / Cq);
    int t   = tok % Tq;
    const float4* x4 = (const float4*)x;
    float4 xc = x4[i4];
    float4 xp = (t==0) ? make_float4(0,0,0,0) : x4[i4 - Cq/4];
    float4 dx = make_float4(xp.x-xc.x, xp.y-xc.y, xp.z-xc.z, xp.w-xc.w);
    size_t c4 = i4 % (Cq/4);
    #define MIX1(COEF, OUT) { \
        float4 cf = ((const float4*)COEF)[c4]; \
        float4 o = make_float4(to_tf32(xc.x + dx.x*cf.x), to_tf32(xc.y + dx.y*cf.y), \
                               to_tf32(xc.z + dx.z*cf.z), to_tf32(xc.w + dx.w*cf.w)); \
        ((float4*)OUT)[i4] = o; }
    MIX1(cr, xr) MIX1(cw, xw) MIX1(ck, xk) MIX1(cv, xv) MIX1(ca, xa) MIX1(cg, xg)
    #undef MIX1
}

// ---------------------------------------------------------------------------
// 2) tf32 tensor-core GEMM: C[m,n] = sum_k A[m,k]*B(n,k)
//    BNK=1: B is [N,K] (weights, x@W.T); BNK=0: B is [K,N] (lora)
//    EPI: 0 none, 1 tanh, 2 sigmoid, 3 w->decay, 4 a-sigmoid, 5 v-mix
//    RND: round output to tf32 (for inputs to subsequent gemms)
//    Tiles: BM=128, BN=128, BK=16, 256 threads, cp.async double buffer.
// ---------------------------------------------------------------------------
template<int EPI,int RND>
__device__ __forceinline__ void epi_store(float val, float* __restrict__ Cm,
                                          int m, int n, int Nd,
                                          const float* __restrict__ bias,
                                          const float* __restrict__ vold,
                                          const float* __restrict__ vfirst)
{
    if (EPI==1) { val = tanhf(val); }
    else if (EPI==2) { val = sigmoidf_(val); }
    else if (EPI==3) {
        float w = bias[n] + val;
        float mneg = -w;
        float sp = fmaxf(mneg,0.f) + log1pf(expf(-fabsf(mneg)));
        float wl = -sp - 0.5f;
        val = expf(-expf(wl));
    }
    else if (EPI==4) { val = sigmoidf_(bias[n] + val); }
    else if (EPI==5) {
        float s  = sigmoidf_(bias[n] + val);
        size_t idx = (size_t)m*Nd + n;
        float vo = vold[idx];
        val = vo + (vfirst[idx] - vo)*s;
    }
    if (RND) val = to_tf32(val);
    Cm[(size_t)m*Nd + n] = val;
}

template<int EPI,int BNK,int RND>
__global__ __launch_bounds__(256,2)
void gemm_tf32(const float* __restrict__ A, const float* __restrict__ Bm,
               float* __restrict__ Cm, int Md, int Nd, int Kd,
               const float* __restrict__ bias,
               const float* __restrict__ vold, const float* __restrict__ vfirst)
{
    constexpr int SZB = BNK ? 128*20 : 16*132;
    __shared__ __align__(16) float As[2][128*20];
    __shared__ __align__(16) float Bs[2][SZB];
    const int bm = blockIdx.y*128, bn = blockIdx.x*128;
    const int tid = threadIdx.x;
    const int lane = tid&31, warp = tid>>5;
    const int wm = (warp&1)*64, wn = (warp>>1)*32;
    const int g = lane>>2, tig = lane&3;

    float acc[4][4][4];
    #pragma unroll
    for (int i=0;i<4;i++)
        #pragma unroll
        for (int j=0;j<4;j++)
            #pragma unroll
            for (int q=0;q<4;q++) acc[i][j][q]=0.f;

    // slab loader
    auto loadSlab = [&](int s, int buf){
        int k0 = s*16;
        #pragma unroll
        for (int i=0;i<2;i++){
            int id  = tid + i*256;
            int row = id>>2, kc = (id&3)*4;
            cpa16(sptr(&As[buf][row*20+kc]),
                  &A[(size_t)(bm+row)*Kd + k0 + kc], 16);
        }
        if (BNK){
            #pragma unroll
            for (int i=0;i<2;i++){
                int id  = tid + i*256;
                int row = id>>2, kc = (id&3)*4;
                int gr  = bn + row;
                int ok  = (gr < Nd) ? 16 : 0;
                int grc = (gr < Nd) ? gr : 0;
                cpa16(sptr(&Bs[buf][row*20+kc]),
                      &Bm[(size_t)grc*Kd + k0 + kc], ok);
            }
        } else {
            #pragma unroll
            for (int i=0;i<2;i++){
                int id  = tid + i*256;
                int row = id>>5, nc = (id&31)*4;
                int gn  = bn + nc;
                int ok  = (gn < Nd) ? 16 : 0;
                int gnc = (gn < Nd) ? gn : 0;
                cpa16(sptr(&Bs[buf][row*132+nc]),
                      &Bm[(size_t)(k0+row)*Nd + gnc], ok);
            }
        }
    };

    auto compute = [&](int buf){
        const uint32_t* Au = (const uint32_t*)As[buf];
        const uint32_t* Bu = (const uint32_t*)Bs[buf];
        #pragma unroll
        for (int kk=0; kk<16; kk+=8){
            uint32_t af[4][4];
            #pragma unroll
            for (int mt=0;mt<4;mt++){
                int m0 = wm + mt*16;
                af[mt][0] = Au[(m0+g  )*20 + kk+tig  ];
                af[mt][1] = Au[(m0+g+8)*20 + kk+tig  ];
                af[mt][2] = Au[(m0+g  )*20 + kk+tig+4];
                af[mt][3] = Au[(m0+g+8)*20 + kk+tig+4];
            }
            uint32_t bf[4][2];
            #pragma unroll
            for (int nt=0;nt<4;nt++){
                int n0 = wn + nt*8;
                if (BNK){
                    bf[nt][0] = Bu[(n0+g)*20 + kk+tig  ];
                    bf[nt][1] = Bu[(n0+g)*20 + kk+tig+4];
                } else {
                    bf[nt][0] = Bu[(kk+tig  )*132 + n0+g];
                    bf[nt][1] = Bu[(kk+tig+4)*132 + n0+g];
                }
            }
            #pragma unroll
            for (int mt=0;mt<4;mt++)
                #pragma unroll
                for (int nt=0;nt<4;nt++)
                    mma8(acc[mt][nt], af[mt], bf[nt]);
        }
    };

    int ns = Kd/16;
    loadSlab(0,0);
    asm volatile("cp.async.commit_group;\n");
    for (int s=0; s<ns; s++){
        int buf = s&1;
        if (s+1 < ns){
            loadSlab(s+1, buf^1);
            asm volatile("cp.async.commit_group;\n");
            asm volatile("cp.async.wait_group 1;\n");
        } else {
            asm volatile("cp.async.wait_group 0;\n");
        }
        __syncthreads();
        compute(buf);
        __syncthreads();
    }

    // epilogue
    #pragma unroll
    for (int mt=0;mt<4;mt++){
        int r0 = bm + wm + mt*16 + g;
        #pragma unroll
        for (int nt=0;nt<4;nt++){
            int n0 = bn + wn + nt*8 + tig*2;
            float* c = acc[mt][nt];
            if (n0 < Nd){
                epi_store<EPI,RND>(c[0], Cm, r0,   n0,   Nd, bias, vold, vfirst);
                epi_store<EPI,RND>(c[1], Cm, r0,   n0+1, Nd, bias, vold, vfirst);
                epi_store<EPI,RND>(c[2], Cm, r0+8, n0,   Nd, bias, vold, vfirst);
                epi_store<EPI,RND>(c[3], Cm, r0+8, n0+1, Nd, bias, vold, vfirst);
            }
        }
    }
}

// ---------------------------------------------------------------------------
// 3) kk normalize + k transform
// ---------------------------------------------------------------------------
__global__ void kk_kernel(float* __restrict__ k, const float* __restrict__ a,
                          const float* __restrict__ k_k, const float* __restrict__ k_a,
                          float* __restrict__ kk)
{
    int gw   = blockIdx.x*8 + (threadIdx.x>>5);
    int lane = threadIdx.x & 31;
    int m = gw >> 5;
    int h = gw & 31;
    size_t base = (size_t)m*Cq + h*HSq;
    int c0 = h*HSq + lane, c1 = c0 + 32;
    float k0 = k[base+lane], k1 = k[base+lane+32];
    float kk0 = k0*k_k[c0], kk1 = k1*k_k[c1];
    float s = kk0*kk0 + kk1*kk1;
    #pragma unroll
    for (int off=16; off; off>>=1) s += __shfl_xor_sync(0xffffffffu, s, off);
    float inv = 1.0f / fmaxf(sqrtf(s), 1e-12f);
    kk[base+lane]    = kk0*inv;
    kk[base+lane+32] = kk1*inv;
    float a0 = a[base+lane], a1 = a[base+lane+32];
    k[base+lane]    = k0*(1.0f + (a0-1.0f)*k_a[c0]);
    k[base+lane+32] = k1*(1.0f + (a1-1.0f)*k_a[c1]);
}

// ---------------------------------------------------------------------------
// 4) WKV7 sequential scan (one block per (b,h), 64 threads)
// ---------------------------------------------------------------------------
__global__ __launch_bounds__(64)
void wkv_kernel(const float* __restrict__ r, const float* __restrict__ wd,
                const float* __restrict__ k, const float* __restrict__ v,
                const float* __restrict__ kkp, const float* __restrict__ ap,
                float* __restrict__ y)
{
    int bh = blockIdx.x;
    int b = bh >> 5;
    int h = bh & 31;
    int i = threadIdx.x;
    __shared__ __align__(16) float sr[64], sw[64], sk[64], sa[64], sb[64];
    float st[64];
    #pragma unroll
    for (int j=0;j<64;j++) st[j]=0.f;
    size_t base = ((size_t)b*Tq)*Cq + (size_t)h*HSq;

    for (int t=0; t<Tq; t++) {
        size_t o = base + (size_t)t*Cq;
        float kkv = kkp[o+i];
        sr[i] = r[o+i];
        sw[i] = wd[o+i];
        sk[i] = k[o+i];
        sa[i] = -kkv;
        sb[i] = kkv * ap[o+i];
        float vv = v[o+i];
        __syncthreads();

        float s0=0,s1=0,s2=0,s3=0;
        const float4* A4 = (const float4*)sa;
        #pragma unroll
        for (int j=0;j<16;j++) {
            float4 a4 = A4[j];
            s0 += st[4*j+0]*a4.x; s1 += st[4*j+1]*a4.y;
            s2 += st[4*j+2]*a4.z; s3 += st[4*j+3]*a4.w;
        }
        float sav = (s0+s1)+(s2+s3);

        const float4* W4=(const float4*)sw; const float4* K4=(const float4*)sk;
        const float4* B4=(const float4*)sb; const float4* R4=(const float4*)sr;
        float o0=0,o1=0,o2=0,o3=0;
        #pragma unroll
        for (int j=0;j<16;j++) {
            float4 w4=W4[j], k4=K4[j], b4=B4[j], r4=R4[j];
            float t0 = st[4*j+0]*w4.x + vv*k4.x + sav*b4.x;
            float t1 = st[4*j+1]*w4.y + vv*k4.y + sav*b4.y;
            float t2 = st[4*j+2]*w4.z + vv*k4.z + sav*b4.z;
            float t3 = st[4*j+3]*w4.w + vv*k4.w + sav*b4.w;
            st[4*j+0]=t0; st[4*j+1]=t1; st[4*j+2]=t2; st[4*j+3]=t3;
            o0 += t0*r4.x; o1 += t1*r4.y; o2 += t2*r4.z; o3 += t3*r4.w;
        }
        y[o+i] = (o0+o1)+(o2+o3);
        __syncthreads();
    }
}

// ---------------------------------------------------------------------------
// 5) GroupNorm + bonus + gate -> z (tf32-rounded for Wo gemm)
// ---------------------------------------------------------------------------
__global__ void gn_kernel(const float* __restrict__ y, const float* __restrict__ r,
                          const float* __restrict__ k, const float* __restrict__ v,
                          const float* __restrict__ g,
                          const float* __restrict__ lnw, const float* __restrict__ lnb,
                          const float* __restrict__ r_k, float* __restrict__ z)
{
    int gw   = blockIdx.x*8 + (threadIdx.x>>5);
    int lane = threadIdx.x & 31;
    int m = gw >> 5;
    int h = gw & 31;
    size_t base = (size_t)m*Cq + h*HSq;
    int c0 = h*HSq + lane, c1 = c0 + 32;
    float y0=y[base+lane], y1=y[base+lane+32];
    float r0=r[base+lane], r1=r[base+lane+32];
    float k0=k[base+lane], k1=k[base+lane+32];
    float sum = y0+y1;
    float sq  = y0*y0 + y1*y1;
    float dot = r0*k0*r_k[c0] + r1*k1*r_k[c1];
    #pragma unroll
    for (int off=16; off; off>>=1) {
        sum += __shfl_xor_sync(0xffffffffu, sum, off);
        sq  += __shfl_xor_sync(0xffffffffu, sq , off);
        dot += __shfl_xor_sync(0xffffffffu, dot, off);
    }
    float mean = sum * (1.0f/64.0f);
    float var  = sq * (1.0f/64.0f) - mean*mean;
    float inv  = rsqrtf(var + EPS_GN);
    float v0=v[base+lane], v1=v[base+lane+32];
    float g0=g[base+lane], g1=g[base+lane+32];
    float z0 = ((y0-mean)*inv*lnw[c0] + lnb[c0] + dot*v0) * g0;
    float z1 = ((y1-mean)*inv*lnw[c1] + lnb[c1] + dot*v1) * g1;
    z[base+lane]    = to_tf32(z0);
    z[base+lane+32] = to_tf32(z1);
}

// ---------------------------------------------------------------------------
// Launch
// ---------------------------------------------------------------------------
extern "C" void kernel_launch(void* const* d_in, const int* in_sizes, int n_in,
                              void* d_out, int out_size)
{
    const float* x       = (const float*)d_in[0];
    const float* v_first = (const float*)d_in[1];
    const float* x_r = (const float*)d_in[2];
    const float* x_w = (const float*)d_in[3];
    const float* x_k = (const float*)d_in[4];
    const float* x_v = (const float*)d_in[5];
    const float* x_a = (const float*)d_in[6];
    const float* x_g = (const float*)d_in[7];
    const float* w0  = (const float*)d_in[8];
    const float* w1  = (const float*)d_in[9];
    const float* w2  = (const float*)d_in[10];
    const float* a0  = (const float*)d_in[11];
    const float* a1  = (const float*)d_in[12];
    const float* a2  = (const float*)d_in[13];
    const float* v0  = (const float*)d_in[14];
    const float* v1  = (const float*)d_in[15];
    const float* v2  = (const float*)d_in[16];
    const float* g1  = (const float*)d_in[17];
    const float* g2  = (const float*)d_in[18];
    const float* k_k = (const float*)d_in[19];
    const float* k_a = (const float*)d_in[20];
    const float* r_k = (const float*)d_in[21];
    const float* Wr  = (const float*)d_in[22];
    const float* Wk  = (const float*)d_in[23];
    const float* Wv  = (const float*)d_in[24];
    const float* Wo  = (const float*)d_in[25];
    const float* lnw = (const float*)d_in[26];
    const float* lnb = (const float*)d_in[27];
    float* out = (float*)d_out;

    float *xr,*xw,*xk,*xv,*xa,*xg,*rB,*kB,*vB,*dec,*aB,*gB,*kkB,*yB,*zB,*tw,*ta,*tv,*tg;
    float *Wrt,*Wkt,*Wvt,*Wot,*w1t,*w2t,*a1t,*a2t,*v1t,*v2t,*g1t,*g2t;
    cudaGetSymbolAddress((void**)&xr , g_xr);
    cudaGetSymbolAddress((void**)&xw , g_xw);
    cudaGetSymbolAddress((void**)&xk , g_xk);
    cudaGetSymbolAddress((void**)&xv , g_xv);
    cudaGetSymbolAddress((void**)&xa , g_xa);
    cudaGetSymbolAddress((void**)&xg , g_xg);
    cudaGetSymbolAddress((void**)&rB , g_r);
    cudaGetSymbolAddress((void**)&kB , g_k);
    cudaGetSymbolAddress((void**)&vB , g_v);
    cudaGetSymbolAddress((void**)&dec, g_dec);
    cudaGetSymbolAddress((void**)&aB , g_a);
    cudaGetSymbolAddress((void**)&gB , g_g);
    cudaGetSymbolAddress((void**)&kkB, g_kk);
    cudaGetSymbolAddress((void**)&yB , g_y);
    cudaGetSymbolAddress((void**)&zB , g_z);
    cudaGetSymbolAddress((void**)&tw , g_tw);
    cudaGetSymbolAddress((void**)&ta , g_ta);
    cudaGetSymbolAddress((void**)&tv , g_tv);
    cudaGetSymbolAddress((void**)&tg , g_tg);
    cudaGetSymbolAddress((void**)&Wrt, g_Wrt);
    cudaGetSymbolAddress((void**)&Wkt, g_Wkt);
    cudaGetSymbolAddress((void**)&Wvt, g_Wvt);
    cudaGetSymbolAddress((void**)&Wot, g_Wot);
    cudaGetSymbolAddress((void**)&w1t, g_w1t);
    cudaGetSymbolAddress((void**)&w2t, g_w2t);
    cudaGetSymbolAddress((void**)&a1t, g_a1t);
    cudaGetSymbolAddress((void**)&a2t, g_a2t);
    cudaGetSymbolAddress((void**)&v1t, g_v1t);
    cudaGetSymbolAddress((void**)&v2t, g_v2t);
    cudaGetSymbolAddress((void**)&g1t, g_g1t);
    cudaGetSymbolAddress((void**)&g2t, g_g2t);

    // 0) round weights to tf32
    #define RND(IN,OUT,N) round_kernel<<<(unsigned)(((N)/4 + 255)/256), 256>>>(IN, OUT, (size_t)(N)/4);
    RND(Wr, Wrt, (size_t)Cq*Cq) RND(Wk, Wkt, (size_t)Cq*Cq)
    RND(Wv, Wvt, (size_t)Cq*Cq) RND(Wo, Wot, (size_t)Cq*Cq)
    RND(w1, w1t, (size_t)Cq*DW) RND(w2, w2t, (size_t)DW*Cq)
    RND(a1, a1t, (size_t)Cq*DA) RND(a2, a2t, (size_t)DA*Cq)
    RND(v1, v1t, (size_t)Cq*DV) RND(v2, v2t, (size_t)DV*Cq)
    RND(g1, g1t, (size_t)Cq*DG) RND(g2, g2t, (size_t)DG*Cq)
    #undef RND

    // 1) token-shift mixes (tf32-rounded)
    mix_kernel<<<(unsigned)((BTC/4 + 255)/256), 256>>>(x, x_r,x_w,x_k,x_v,x_a,x_g,
                                                       xr,xw,xk,xv,xa,xg);

    dim3 gBig((Cq+127)/128, Mq/128);       // (16, 64)
    // 2) big projections (B is [N,K])
    gemm_tf32<0,1,0><<<gBig,256>>>(xr, Wrt, rB, Mq, Cq, Cq, nullptr,nullptr,nullptr);
    gemm_tf32<0,1,0><<<gBig,256>>>(xk, Wkt, kB, Mq, Cq, Cq, nullptr,nullptr,nullptr);
    gemm_tf32<0,1,0><<<gBig,256>>>(xv, Wvt, vB, Mq, Cq, Cq, nullptr,nullptr,nullptr);

    // 3) loras (B is [K,N]); intermediates tf32-rounded
    gemm_tf32<1,0,1><<<dim3((DW+127)/128, Mq/128),256>>>(xw, w1t, tw, Mq, DW, Cq, nullptr,nullptr,nullptr);
    gemm_tf32<3,0,0><<<gBig,256>>>(tw, w2t, dec, Mq, Cq, DW, w0, nullptr,nullptr);
    gemm_tf32<0,0,1><<<dim3((DA+127)/128, Mq/128),256>>>(xa, a1t, ta, Mq, DA, Cq, nullptr,nullptr,nullptr);
    gemm_tf32<4,0,0><<<gBig,256>>>(ta, a2t, aB, Mq, Cq, DA, a0, nullptr,nullptr);
    gemm_tf32<0,0,1><<<dim3((DV+127)/128, Mq/128),256>>>(xv, v1t, tv, Mq, DV, Cq, nullptr,nullptr,nullptr);
    gemm_tf32<5,0,0><<<gBig,256>>>(tv, v2t, vB, Mq, Cq, DV, v0, vB, v_first);
    gemm_tf32<2,0,1><<<dim3((DG+127)/128, Mq/128),256>>>(xg, g1t, tg, Mq, DG, Cq, nullptr,nullptr,nullptr);
    gemm_tf32<0,0,0><<<gBig,256>>>(tg, g2t, gB, Mq, Cq, DG, nullptr,nullptr,nullptr);

    // 4) kk normalize + k transform
    kk_kernel<<<Mq*Hq/8, 256>>>(kB, aB, k_k, k_a, kkB);

    // 5) WKV7 scan
    wkv_kernel<<<Bq*Hq, 64>>>(rB, dec, kB, vB, kkB, aB, yB);

    // 6) GroupNorm + bonus + gate (tf32-rounded z)
    gn_kernel<<<Mq*Hq/8, 256>>>(yB, rB, kB, vB, gB, lnw, lnb, r_k, zB);

    // 7) output projection
    gemm_tf32<0,1,0><<<gBig,256>>>(zB, Wot, out, Mq, Cq, Cq, nullptr,nullptr,nullptr);
}

// round 5
// speedup vs baseline: 3.2666x; 1.6141x over previous
#include <cuda_runtime.h>
#include <cuda_fp16.h>
#include <math.h>
#include <stdint.h>

// Problem constants
#define Bq 4
#define Tq 2048
#define Cq 2048
#define Hq 32
#define HSq 64
#define Mq (Bq*Tq)            // 8192 tokens
#define DW 128
#define DA 128
#define DG 224
#define DV 64
#define EPS_GN 0.00064f

// ---------------------------------------------------------------------------
// Scratch (static device globals; zero-initialized at module load)
// ---------------------------------------------------------------------------
#define BTC ((size_t)Mq*Cq)
// fp16 GEMM inputs
__device__ __half h_xr[BTC];
__device__ __half h_xw[BTC];
__device__ __half h_xk[BTC];
__device__ __half h_xv[BTC];
__device__ __half h_xa[BTC];
__device__ __half h_xg[BTC];
__device__ __half h_z [BTC];
__device__ __half h_Wr[(size_t)Cq*Cq];
__device__ __half h_Wk[(size_t)Cq*Cq];
__device__ __half h_Wv[(size_t)Cq*Cq];
__device__ __half h_Wo[(size_t)Cq*Cq];
__device__ __half h_w1[(size_t)128*Cq];   // [DW pad128][C]
__device__ __half h_w2[(size_t)Cq*DW];    // [C][DW]
__device__ __half h_a1[(size_t)128*Cq];
__device__ __half h_a2[(size_t)Cq*DA];
__device__ __half h_v1[(size_t)128*Cq];   // [DV pad128][C]
__device__ __half h_v2[(size_t)Cq*DV];
__device__ __half h_g1[(size_t)256*Cq];   // [DG pad256][C]
__device__ __half h_g2[(size_t)Cq*DG];
__device__ __half h_tw[(size_t)Mq*DW];
__device__ __half h_ta[(size_t)Mq*DA];
__device__ __half h_tv[(size_t)Mq*DV];
__device__ __half h_tg[(size_t)Mq*DG];
// fp32 intermediates
__device__ float g_r [BTC];
__device__ float g_k [BTC];
__device__ float g_v [BTC];
__device__ float g_dec[BTC];
__device__ float g_a [BTC];
__device__ float g_g [BTC];
__device__ float g_kk[BTC];
__device__ float g_y [BTC];

__device__ __forceinline__ float sigmoidf_(float x){ return 1.0f/(1.0f+expf(-x)); }

__device__ __forceinline__ void cpa16(uint32_t s, const void* g){
    asm volatile("cp.async.cg.shared.global [%0], [%1], 16;\n" :: "r"(s), "l"(g));
}
__device__ __forceinline__ void ldsm_x4(uint32_t* r, uint32_t addr){
    asm volatile("ldmatrix.sync.aligned.m8n8.x4.shared.b16 {%0,%1,%2,%3}, [%4];"
        : "=r"(r[0]),"=r"(r[1]),"=r"(r[2]),"=r"(r[3]) : "r"(addr));
}
__device__ __forceinline__ void mma16(float* c, const uint32_t* a, const uint32_t* b){
    asm volatile("mma.sync.aligned.m16n8k16.row.col.f32.f16.f16.f32 "
        "{%0,%1,%2,%3},{%4,%5,%6,%7},{%8,%9},{%0,%1,%2,%3};\n"
        : "+f"(c[0]),"+f"(c[1]),"+f"(c[2]),"+f"(c[3])
        : "r"(a[0]),"r"(a[1]),"r"(a[2]),"r"(a[3]),"r"(b[0]),"r"(b[1]));
}

// ---------------------------------------------------------------------------
// Prep: f32 -> f16 copy; transpose f32[R][C] -> f16[C][R]
// ---------------------------------------------------------------------------
__global__ void f2h_kernel(const float* __restrict__ in, __half* __restrict__ out, size_t n4)
{
    size_t i = (size_t)blockIdx.x*blockDim.x + threadIdx.x;
    if (i >= n4) return;
    float4 v = ((const float4*)in)[i];
    ((__half2*)out)[i*2  ] = __floats2half2_rn(v.x, v.y);
    ((__half2*)out)[i*2+1] = __floats2half2_rn(v.z, v.w);
}

__global__ void transpose_h(const float* __restrict__ in, __half* __restrict__ out, int R, int C)
{
    __shared__ float tile[32][33];
    int cb = blockIdx.x*32, rb = blockIdx.y*32;
    int c = cb + threadIdx.x;
    #pragma unroll
    for (int i=threadIdx.y; i<32; i+=8){
        int r = rb + i;
        if (r<R && c<C) tile[i][threadIdx.x] = in[(size_t)r*C + c];
    }
    __syncthreads();
    int r2 = rb + threadIdx.x;
    #pragma unroll
    for (int i=threadIdx.y; i<32; i+=8){
        int c2 = cb + i;
        if (r2<R && c2<C) out[(size_t)c2*R + r2] = __float2half_rn(tile[threadIdx.x][i]);
    }
}

// ---------------------------------------------------------------------------
// Token-shift mix -> fp16 outputs
// ---------------------------------------------------------------------------
__global__ void mix_kernel(const float* __restrict__ x,
                           const float* __restrict__ cr, const float* __restrict__ cw,
                           const float* __restrict__ ck, const float* __restrict__ cv,
                           const float* __restrict__ ca, const float* __restrict__ cg,
                           __half* __restrict__ xr, __half* __restrict__ xw,
                           __half* __restrict__ xk, __half* __restrict__ xv,
                           __half* __restrict__ xa, __half* __restrict__ xg)
{
    size_t i4 = (size_t)blockIdx.x*blockDim.x + threadIdx.x;
    size_t n4 = BTC/4;
    if (i4 >= n4) return;
    size_t flat = i4*4;
    int tok = (int)(flat / Cq);
    int t   = tok % Tq;
    const float4* x4 = (const float4*)x;
    float4 xc = x4[i4];
    float4 xp = (t==0) ? make_float4(0,0,0,0) : x4[i4 - Cq/4];
    float4 dx = make_float4(xp.x-xc.x, xp.y-xc.y, xp.z-xc.z, xp.w-xc.w);
    size_t c4 = i4 % (Cq/4);
    #define MIX1(COEF, OUT) { \
        float4 cf = ((const float4*)COEF)[c4]; \
        ((__half2*)OUT)[i4*2  ] = __floats2half2_rn(xc.x + dx.x*cf.x, xc.y + dx.y*cf.y); \
        ((__half2*)OUT)[i4*2+1] = __floats2half2_rn(xc.z + dx.z*cf.z, xc.w + dx.w*cf.w); }
    MIX1(cr, xr) MIX1(cw, xw) MIX1(ck, xk) MIX1(cv, xv) MIX1(ca, xa) MIX1(cg, xg)
    #undef MIX1
}

// ---------------------------------------------------------------------------
// Epilogue transform: 0 none, 1 tanh, 2 sigmoid, 3 w->decay, 4 a-sigm, 5 v-mix
// ---------------------------------------------------------------------------
template<int EPI>
__device__ __forceinline__ float epi_val(float val, int m, int n, int Nd,
                                         const float* __restrict__ bias,
                                         const float* __restrict__ vold,
                                         const float* __restrict__ vfirst)
{
    if (EPI==1) { val = tanhf(val); }
    else if (EPI==2) { val = sigmoidf_(val); }
    else if (EPI==3) {
        float w = bias[n] + val;
        float mneg = -w;
        float sp = fmaxf(mneg,0.f) + log1pf(expf(-fabsf(mneg)));
        float wl = -sp - 0.5f;
        val = expf(-expf(wl));
    }
    else if (EPI==4) { val = sigmoidf_(bias[n] + val); }
    else if (EPI==5) {
        float s  = sigmoidf_(bias[n] + val);
        size_t idx = (size_t)m*Nd + n;
        float vo = vold[idx];
        val = vo + (vfirst[idx] - vo)*s;
    }
    return val;
}

// ---------------------------------------------------------------------------
// fp16 tensor-core GEMM: C[m,n] = sum_k A[m,k] * B[n,k]
// CTA 128x128, BK=32, 4-stage cp.async, 8 warps (2Mx4N), warp 64x32.
// A and B both K-contiguous in smem; both fed with NON-trans ldmatrix
// (row.col mma: B fragment = two consecutive k at fixed n = exactly what
//  non-trans ldmatrix yields on an [n][k] tile).
// RND=1 -> write __half, else float.
// ---------------------------------------------------------------------------
#define GSTAGES 4
#define STAGE_HB 10240           // bytes: 128 rows * 40 halves * 2B
#define STAGE_BYTES (2*STAGE_HB)

template<int EPI,int RND>
__global__ __launch_bounds__(256,2)
void gemm_h(const __half* __restrict__ A, const __half* __restrict__ Bw,
            void* __restrict__ Cm, int Nd, int Kd,
            const float* __restrict__ bias,
            const float* __restrict__ vold, const float* __restrict__ vfirst)
{
    extern __shared__ __align__(128) char smc[];
    const int tid = threadIdx.x;
    const int lane = tid&31, warp = tid>>5;
    const int bm = blockIdx.y*128, bn = blockIdx.x*128;
    const int wm = (warp&1)*64, wn = (warp>>1)*32;
    const int g = lane>>2, tig = lane&3;
    const uint32_t sbase = (uint32_t)__cvta_generic_to_shared(smc);

    // per-lane ldmatrix coords (non-trans x4 matrix order: lanes 0-7 m0, 8-15 m1, 16-23 m2, 24-31 m3)
    // A: m0 rows0-7/k0-7, m1 rows8-15/k0-7, m2 rows0-7/k8-15, m3 rows8-15/k8-15 -> a0..a3
    const int arow = wm + (lane&7) + ((lane>>3)&1)*8;   // + mt*16
    const int akof = (lane>>4)*8;
    // B: m0 n0-7/k0-7, m1 n0-7/k8-15, m2 n8-15/k0-7, m3 n8-15/k8-15
    //    -> bf = {grp0 b0, grp0 b1, grp1 b0, grp1 b1}
    const int brow = wn + (lane&7) + (lane>>4)*8;       // + p*16
    const int bkof = ((lane>>3)&1)*8;

    float acc[4][4][4];
    #pragma unroll
    for (int i=0;i<4;i++)
        #pragma unroll
        for (int j=0;j<4;j++)
            #pragma unroll
            for (int q=0;q<4;q++) acc[i][j][q]=0.f;

    const int NS = Kd >> 5;

    auto loadSlab = [&](int s, int st){
        const uint32_t sb = sbase + st*STAGE_BYTES;
        const int k0 = s*32;
        #pragma unroll
        for (int i=0;i<2;i++){
            int id  = tid + i*256;
            int row = id>>2, c16 = id&3;
            cpa16(sb + row*80 + c16*16,
                  &A[(size_t)(bm+row)*Kd + k0 + c16*8]);
            cpa16(sb + STAGE_HB + row*80 + c16*16,
                  &Bw[(size_t)(bn+row)*Kd + k0 + c16*8]);
        }
    };
    auto compute = [&](int st){
        const uint32_t sb = sbase + st*STAGE_BYTES;
        #pragma unroll
        for (int ks=0; ks<2; ks++){
            uint32_t af[4][4], bf[2][4];
            #pragma unroll
            for (int mt=0;mt<4;mt++)
                ldsm_x4(af[mt], sb + ((arow+mt*16)*40 + akof + ks*16)*2);
            #pragma unroll
            for (int p=0;p<2;p++)
                ldsm_x4(bf[p], sb + STAGE_HB + ((brow+p*16)*40 + bkof + ks*16)*2);
            #pragma unroll
            for (int mt=0;mt<4;mt++)
                #pragma unroll
                for (int nt=0;nt<4;nt++)
                    mma16(acc[mt][nt], af[mt], &bf[nt>>1][(nt&1)*2]);
        }
    };

    #pragma unroll
    for (int i=0;i<GSTAGES-1;i++){
        if (i<NS) loadSlab(i,i);
        asm volatile("cp.async.commit_group;\n");
    }
    for (int s=0;s<NS;s++){
        int ld = s + GSTAGES-1;
        if (ld < NS) loadSlab(ld, ld&3);
        asm volatile("cp.async.commit_group;\n");
        asm volatile("cp.async.wait_group %0;\n" :: "n"(GSTAGES-1));
        __syncthreads();
        compute(s&3);
        __syncthreads();
    }

    // epilogue
    #pragma unroll
    for (int mt=0;mt<4;mt++){
        int r0 = bm + wm + mt*16 + g;
        #pragma unroll
        for (int nt=0;nt<4;nt++){
            int n0 = bn + wn + nt*8 + tig*2;
            if (n0 < Nd){
                float* c = acc[mt][nt];
                float v00 = epi_val<EPI>(c[0], r0,   n0,   Nd, bias, vold, vfirst);
                float v01 = epi_val<EPI>(c[1], r0,   n0+1, Nd, bias, vold, vfirst);
                float v10 = epi_val<EPI>(c[2], r0+8, n0,   Nd, bias, vold, vfirst);
                float v11 = epi_val<EPI>(c[3], r0+8, n0+1, Nd, bias, vold, vfirst);
                if (RND){
                    __half* O = (__half*)Cm;
                    *(__half2*)&O[(size_t)r0*Nd + n0]     = __floats2half2_rn(v00, v01);
                    *(__half2*)&O[(size_t)(r0+8)*Nd + n0] = __floats2half2_rn(v10, v11);
                } else {
                    float* O = (float*)Cm;
                    *(float2*)&O[(size_t)r0*Nd + n0]     = make_float2(v00, v01);
                    *(float2*)&O[(size_t)(r0+8)*Nd + n0] = make_float2(v10, v11);
                }
            }
        }
    }
}

// ---------------------------------------------------------------------------
// kk normalize + k transform
// ---------------------------------------------------------------------------
__global__ void kk_kernel(float* __restrict__ k, const float* __restrict__ a,
                          const float* __restrict__ k_k, const float* __restrict__ k_a,
                          float* __restrict__ kk)
{
    int gw   = blockIdx.x*8 + (threadIdx.x>>5);
    int lane = threadIdx.x & 31;
    int m = gw >> 5;
    int h = gw & 31;
    size_t base = (size_t)m*Cq + h*HSq;
    int c0 = h*HSq + lane, c1 = c0 + 32;
    float k0 = k[base+lane], k1 = k[base+lane+32];
    float kk0 = k0*k_k[c0], kk1 = k1*k_k[c1];
    float s = kk0*kk0 + kk1*kk1;
    #pragma unroll
    for (int off=16; off; off>>=1) s += __shfl_xor_sync(0xffffffffu, s, off);
    float inv = 1.0f / fmaxf(sqrtf(s), 1e-12f);
    kk[base+lane]    = kk0*inv;
    kk[base+lane+32] = kk1*inv;
    float a0 = a[base+lane], a1 = a[base+lane+32];
    k[base+lane]    = k0*(1.0f + (a0-1.0f)*k_a[c0]);
    k[base+lane+32] = k1*(1.0f + (a1-1.0f)*k_a[c1]);
}

// ---------------------------------------------------------------------------
// WKV7 scan (one block per (b,h), 64 threads, register-prefetched)
// ---------------------------------------------------------------------------
__global__ __launch_bounds__(64)
void wkv_kernel(const float* __restrict__ r, const float* __restrict__ wd,
                const float* __restrict__ k, const float* __restrict__ v,
                const float* __restrict__ kkp, const float* __restrict__ ap,
                float* __restrict__ y)
{
    int bh = blockIdx.x;
    int b = bh >> 5;
    int h = bh & 31;
    int i = threadIdx.x;
    __shared__ __align__(16) float sr[64], sw[64], sk[64], sa[64], sb[64];
    float st[64];
    #pragma unroll
    for (int j=0;j<64;j++) st[j]=0.f;
    size_t base = ((size_t)b*Tq)*Cq + (size_t)h*HSq;

    size_t o = base;
    float rv=r[o+i], wv=wd[o+i], kv=k[o+i], kkv=kkp[o+i], av=ap[o+i], vv=v[o+i];

    for (int t=0; t<Tq; t++) {
        sr[i]=rv; sw[i]=wv; sk[i]=kv; sa[i]=-kkv; sb[i]=kkv*av;
        float vcur = vv;
        __syncthreads();

        size_t on = o + Cq;
        if (t+1 < Tq){
            rv=r[on+i]; wv=wd[on+i]; kv=k[on+i]; kkv=kkp[on+i]; av=ap[on+i]; vv=v[on+i];
        }

        float s0=0,s1=0,s2=0,s3=0;
        const float4* A4 = (const float4*)sa;
        #pragma unroll
        for (int j=0;j<16;j++) {
            float4 a4 = A4[j];
            s0 += st[4*j+0]*a4.x; s1 += st[4*j+1]*a4.y;
            s2 += st[4*j+2]*a4.z; s3 += st[4*j+3]*a4.w;
        }
        float sav = (s0+s1)+(s2+s3);

        const float4* W4=(const float4*)sw; const float4* K4=(const float4*)sk;
        const float4* B4=(const float4*)sb; const float4* R4=(const float4*)sr;
        float o0=0,o1=0,o2=0,o3=0;
        #pragma unroll
        for (int j=0;j<16;j++) {
            float4 w4=W4[j], k4=K4[j], b4=B4[j], r4=R4[j];
            float t0 = st[4*j+0]*w4.x + vcur*k4.x + sav*b4.x;
            float t1 = st[4*j+1]*w4.y + vcur*k4.y + sav*b4.y;
            float t2 = st[4*j+2]*w4.z + vcur*k4.z + sav*b4.z;
            float t3 = st[4*j+3]*w4.w + vcur*k4.w + sav*b4.w;
            st[4*j+0]=t0; st[4*j+1]=t1; st[4*j+2]=t2; st[4*j+3]=t3;
            o0 += t0*r4.x; o1 += t1*r4.y; o2 += t2*r4.z; o3 += t3*r4.w;
        }
        y[o+i] = (o0+o1)+(o2+o3);
        o = on;
        __syncthreads();
    }
}

// ---------------------------------------------------------------------------
// GroupNorm + bonus + gate -> z (fp16 for Wo gemm)
// ---------------------------------------------------------------------------
__global__ void gn_kernel(const float* __restrict__ y, const float* __restrict__ r,
                          const float* __restrict__ k, const float* __restrict__ v,
                          const float* __restrict__ g,
                          const float* __restrict__ lnw, const float* __restrict__ lnb,
                          const float* __restrict__ r_k, __half* __restrict__ z)
{
    int gw   = blockIdx.x*8 + (threadIdx.x>>5);
    int lane = threadIdx.x & 31;
    int m = gw >> 5;
    int h = gw & 31;
    size_t base = (size_t)m*Cq + h*HSq;
    int c0 = h*HSq + lane, c1 = c0 + 32;
    float y0=y[base+lane], y1=y[base+lane+32];
    float r0=r[base+lane], r1=r[base+lane+32];
    float k0=k[base+lane], k1=k[base+lane+32];
    float sum = y0+y1;
    float sq  = y0*y0 + y1*y1;
    float dot = r0*k0*r_k[c0] + r1*k1*r_k[c1];
    #pragma unroll
    for (int off=16; off; off>>=1) {
        sum += __shfl_xor_sync(0xffffffffu, sum, off);
        sq  += __shfl_xor_sync(0xffffffffu, sq , off);
        dot += __shfl_xor_sync(0xffffffffu, dot, off);
    }
    float mean = sum * (1.0f/64.0f);
    float var  = sq * (1.0f/64.0f) - mean*mean;
    float inv  = rsqrtf(var + EPS_GN);
    float v0=v[base+lane], v1=v[base+lane+32];
    float g0=g[base+lane], g1=g[base+lane+32];
    float z0 = ((y0-mean)*inv*lnw[c0] + lnb[c0] + dot*v0) * g0;
    float z1 = ((y1-mean)*inv*lnw[c1] + lnb[c1] + dot*v1) * g1;
    z[base+lane]    = __float2half_rn(z0);
    z[base+lane+32] = __float2half_rn(z1);
}

// ---------------------------------------------------------------------------
// Host helpers
// ---------------------------------------------------------------------------
template<int EPI,int RND>
static void rg(const __half* A, const __half* Bw, void* C, int Nd, int Kd,
               const float* bias, const float* vold, const float* vfirst)
{
    cudaFuncSetAttribute(gemm_h<EPI,RND>, cudaFuncAttributeMaxDynamicSharedMemorySize,
                         GSTAGES*STAGE_BYTES);
    dim3 grid((Nd+127)/128, Mq/128);
    gemm_h<EPI,RND><<<grid, 256, GSTAGES*STAGE_BYTES>>>(A, Bw, C, Nd, Kd, bias, vold, vfirst);
}

// ---------------------------------------------------------------------------
// Launch
// ---------------------------------------------------------------------------
extern "C" void kernel_launch(void* const* d_in, const int* in_sizes, int n_in,
                              void* d_out, int out_size)
{
    const float* x       = (const float*)d_in[0];
    const float* v_first = (const float*)d_in[1];
    const float* x_r = (const float*)d_in[2];
    const float* x_w = (const float*)d_in[3];
    const float* x_k = (const float*)d_in[4];
    const float* x_v = (const float*)d_in[5];
    const float* x_a = (const float*)d_in[6];
    const float* x_g = (const float*)d_in[7];
    const float* w0  = (const float*)d_in[8];
    const float* w1  = (const float*)d_in[9];
    const float* w2  = (const float*)d_in[10];
    const float* a0  = (const float*)d_in[11];
    const float* a1  = (const float*)d_in[12];
    const float* a2  = (const float*)d_in[13];
    const float* v0  = (const float*)d_in[14];
    const float* v1  = (const float*)d_in[15];
    const float* v2  = (const float*)d_in[16];
    const float* g1  = (const float*)d_in[17];
    const float* g2  = (const float*)d_in[18];
    const float* k_k = (const float*)d_in[19];
    const float* k_a = (const float*)d_in[20];
    const float* r_k = (const float*)d_in[21];
    const float* Wr  = (const float*)d_in[22];
    const float* Wk  = (const float*)d_in[23];
    const float* Wv  = (const float*)d_in[24];
    const float* Wo  = (const float*)d_in[25];
    const float* lnw = (const float*)d_in[26];
    const float* lnb = (const float*)d_in[27];
    float* out = (float*)d_out;

    __half *xr,*xw,*xk,*xv,*xa,*xg,*zh,*Wrh,*Wkh,*Wvh,*Woh;
    __half *w1h,*w2h,*a1h,*a2h,*v1h,*v2h,*g1h,*g2h,*twh,*tah,*tvh,*tgh;
    float *rB,*kB,*vB,*dec,*aB,*gB,*kkB,*yB;
    cudaGetSymbolAddress((void**)&xr , h_xr);
    cudaGetSymbolAddress((void**)&xw , h_xw);
    cudaGetSymbolAddress((void**)&xk , h_xk);
    cudaGetSymbolAddress((void**)&xv , h_xv);
    cudaGetSymbolAddress((void**)&xa , h_xa);
    cudaGetSymbolAddress((void**)&xg , h_xg);
    cudaGetSymbolAddress((void**)&zh , h_z);
    cudaGetSymbolAddress((void**)&Wrh, h_Wr);
    cudaGetSymbolAddress((void**)&Wkh, h_Wk);
    cudaGetSymbolAddress((void**)&Wvh, h_Wv);
    cudaGetSymbolAddress((void**)&Woh, h_Wo);
    cudaGetSymbolAddress((void**)&w1h, h_w1);
    cudaGetSymbolAddress((void**)&w2h, h_w2);
    cudaGetSymbolAddress((void**)&a1h, h_a1);
    cudaGetSymbolAddress((void**)&a2h, h_a2);
    cudaGetSymbolAddress((void**)&v1h, h_v1);
    cudaGetSymbolAddress((void**)&v2h, h_v2);
    cudaGetSymbolAddress((void**)&g1h, h_g1);
    cudaGetSymbolAddress((void**)&g2h, h_g2);
    cudaGetSymbolAddress((void**)&twh, h_tw);
    cudaGetSymbolAddress((void**)&tah, h_ta);
    cudaGetSymbolAddress((void**)&tvh, h_tv);
    cudaGetSymbolAddress((void**)&tgh, h_tg);
    cudaGetSymbolAddress((void**)&rB , g_r);
    cudaGetSymbolAddress((void**)&kB , g_k);
    cudaGetSymbolAddress((void**)&vB , g_v);
    cudaGetSymbolAddress((void**)&dec, g_dec);
    cudaGetSymbolAddress((void**)&aB , g_a);
    cudaGetSymbolAddress((void**)&gB , g_g);
    cudaGetSymbolAddress((void**)&kkB, g_kk);
    cudaGetSymbolAddress((void**)&yB , g_y);

    // 0) weight prep: big weights f32->f16; lora weights transpose->f16 (K-major)
    #define F2H_(IN,OUT,N) f2h_kernel<<<(unsigned)(((N)/4 + 255)/256), 256>>>(IN, OUT, (size_t)(N)/4);
    F2H_(Wr, Wrh, (size_t)Cq*Cq) F2H_(Wk, Wkh, (size_t)Cq*Cq)
    F2H_(Wv, Wvh, (size_t)Cq*Cq) F2H_(Wo, Woh, (size_t)Cq*Cq)
    #undef F2H_
    dim3 tb(32,8);
    transpose_h<<<dim3((DW+31)/32,(Cq+31)/32), tb>>>(w1, w1h, Cq, DW);   // -> [DW][C]
    transpose_h<<<dim3((Cq+31)/32,(DW+31)/32), tb>>>(w2, w2h, DW, Cq);   // -> [C][DW]
    transpose_h<<<dim3((DA+31)/32,(Cq+31)/32), tb>>>(a1, a1h, Cq, DA);
    transpose_h<<<dim3((Cq+31)/32,(DA+31)/32), tb>>>(a2, a2h, DA, Cq);
    transpose_h<<<dim3((DV+31)/32,(Cq+31)/32), tb>>>(v1, v1h, Cq, DV);
    transpose_h<<<dim3((Cq+31)/32,(DV+31)/32), tb>>>(v2, v2h, DV, Cq);
    transpose_h<<<dim3((DG+31)/32,(Cq+31)/32), tb>>>(g1, g1h, Cq, DG);
    transpose_h<<<dim3((Cq+31)/32,(DG+31)/32), tb>>>(g2, g2h, DG, Cq);

    // 1) token-shift mixes -> fp16
    mix_kernel<<<(unsigned)((BTC/4 + 255)/256), 256>>>(x, x_r,x_w,x_k,x_v,x_a,x_g,
                                                       xr,xw,xk,xv,xa,xg);

    // 2) big projections
    rg<0,0>(xr, Wrh, rB, Cq, Cq, nullptr,nullptr,nullptr);
    rg<0,0>(xk, Wkh, kB, Cq, Cq, nullptr,nullptr,nullptr);
    rg<0,0>(xv, Wvh, vB, Cq, Cq, nullptr,nullptr,nullptr);

    // 3) loras (up -> fp16 intermediate, down -> fp32 + epilogue)
    rg<1,1>(xw, w1h, twh, DW, Cq, nullptr,nullptr,nullptr);
    rg<3,0>(twh, w2h, dec, Cq, DW, w0, nullptr,nullptr);
    rg<0,1>(xa, a1h, tah, DA, Cq, nullptr,nullptr,nullptr);
    rg<4,0>(tah, a2h, aB, Cq, DA, a0, nullptr,nullptr);
    rg<0,1>(xv, v1h, tvh, DV, Cq, nullptr,nullptr,nullptr);
    rg<5,0>(tvh, v2h, vB, Cq, DV, v0, vB, v_first);
    rg<2,1>(xg, g1h, tgh, DG, Cq, nullptr,nullptr,nullptr);
    rg<0,0>(tgh, g2h, gB, Cq, DG, nullptr,nullptr,nullptr);

    // 4) kk normalize + k transform
    kk_kernel<<<Mq*Hq/8, 256>>>(kB, aB, k_k, k_a, kkB);

    // 5) WKV7 scan
    wkv_kernel<<<Bq*Hq, 64>>>(rB, dec, kB, vB, kkB, aB, yB);

    // 6) GroupNorm + bonus + gate -> fp16 z
    gn_kernel<<<Mq*Hq/8, 256>>>(yB, rB, kB, vB, gB, lnw, lnb, r_k, zh);

    // 7) output projection
    rg<0,0>(zh, Woh, out, Cq, Cq, nullptr,nullptr,nullptr);
}